// round 17
// baseline (speedup 1.0000x reference)
#include <cuda_runtime.h>
#include <cuda_bf16.h>
#include <cstdint>
#include <cstddef>

// ---------------------------------------------------------------------------
// GlobalRouters, round 17: K1 v3 — x register-direct (no smem round-trip),
// W via cp.async depth-3 ring, M=64/grid 256, bias in epilogue (K1b removed).
// K2/K3/K0 verbatim from the 124.9us build.
// ---------------------------------------------------------------------------

#define NTOK_TOTAL 16384
#define DDIM       2048
#define DS         64
#define NUSE       1536
#define BATCHES    8
#define OUT_PER_B  1792

// K2 geometry
#define K2_TOK     32
#define K2_BLOCKS  (NTOK_TOTAL / K2_TOK)      // 512
#define BLK_PER_B  (K2_BLOCKS / BATCHES)      // 64
#define NCH2       64
#define NCHUNKS2   (NUSE / NCH2)              // 24
#define EPH        514

// K2 dynamic smem (bytes)
#define OFF_BA     0
#define OFF_BB     16384
#define OFF_E2     32768
#define OFF_Z2     98560
#define OFF_C2     99072
#define K2_SMEM    99200

// K1 dynamic smem: 3 x 16KB W ring buffers (hi@+0, lo@+8192 in each)
#define K1_SMEM    49152
#define K1_NCHUNK  (DDIM / 64)                // 32

#define SWZ(r, b)  (((unsigned)(r) << 7) + ((unsigned)(b) ^ ((((unsigned)(r)) & 7u) << 4)))

// scratch
__device__ __nv_bfloat16 g_embB_hi[NUSE * DS];
__device__ __nv_bfloat16 g_embB_lo[NUSE * DS];
__device__ __nv_bfloat16 g_WB_hi[DS * DDIM];
__device__ __nv_bfloat16 g_WB_lo[DS * DDIM];
__device__ __nv_bfloat16 g_hB_hi[NTOK_TOTAL * DS];
__device__ __nv_bfloat16 g_hB_lo[NTOK_TOTAL * DS];
__device__ float g_part[K2_BLOCKS * NUSE];

// ---- helpers --------------------------------------------------------------
__device__ __forceinline__ uint32_t smem_u32(const void* p) {
    uint32_t a;
    asm("{ .reg .u64 t; cvta.to.shared.u64 t, %1; cvt.u32.u64 %0, t; }"
        : "=r"(a) : "l"(p));
    return a;
}

__device__ __forceinline__ void ldsm4(uint32_t& r0, uint32_t& r1,
                                      uint32_t& r2, uint32_t& r3, uint32_t a) {
    asm volatile("ldmatrix.sync.aligned.m8n8.x4.shared.b16 {%0,%1,%2,%3}, [%4];"
                 : "=r"(r0), "=r"(r1), "=r"(r2), "=r"(r3) : "r"(a));
}

__device__ __forceinline__ void mma16816(float* d, const uint32_t* a,
                                         uint32_t b0, uint32_t b1) {
    asm volatile("mma.sync.aligned.m16n8k16.row.col.f32.bf16.bf16.f32 "
                 "{%0,%1,%2,%3}, {%4,%5,%6,%7}, {%8,%9}, {%0,%1,%2,%3};"
                 : "+f"(d[0]), "+f"(d[1]), "+f"(d[2]), "+f"(d[3])
                 : "r"(a[0]), "r"(a[1]), "r"(a[2]), "r"(a[3]), "r"(b0), "r"(b1));
}

__device__ __forceinline__ uint32_t bits2(__nv_bfloat162 v) {
    return *reinterpret_cast<uint32_t*>(&v);
}

#define CP16(dst, src) \
    asm volatile("cp.async.cg.shared.global [%0], [%1], 16;" \
                 :: "r"(dst), "l"(__cvta_generic_to_global(src)) : "memory")
#define CP_COMMIT() asm volatile("cp.async.commit_group;" ::: "memory")
#define CP_WAIT1()  asm volatile("cp.async.wait_group 1;" ::: "memory")
#define CP_WAIT0()  asm volatile("cp.async.wait_group 0;" ::: "memory")

// ---------------------------------------------------------------------------
// K0: normalize emb + bf16 split, [n][64]
// ---------------------------------------------------------------------------
__global__ void __launch_bounds__(256) k0_norm(const float* __restrict__ emb) {
    int n = blockIdx.x * 8 + (threadIdx.x >> 5);
    int lane = threadIdx.x & 31;
    if (n >= NUSE) return;
    float v0 = emb[n * DS + lane];
    float v1 = emb[n * DS + 32 + lane];
    float ss = v0 * v0 + v1 * v1;
    #pragma unroll
    for (int o = 16; o; o >>= 1) ss += __shfl_xor_sync(0xFFFFFFFFu, ss, o);
    float inv = 1.0f / sqrtf(ss);
    v0 *= inv; v1 *= inv;
    __nv_bfloat16 h0 = __float2bfloat16(v0);
    __nv_bfloat16 h1 = __float2bfloat16(v1);
    g_embB_hi[n * DS + lane]      = h0;
    g_embB_hi[n * DS + 32 + lane] = h1;
    g_embB_lo[n * DS + lane]      = __float2bfloat16(v0 - __bfloat162float(h0));
    g_embB_lo[n * DS + 32 + lane] = __float2bfloat16(v1 - __bfloat162float(h1));
}

// ---------------------------------------------------------------------------
// K0w: split W
// ---------------------------------------------------------------------------
__global__ void __launch_bounds__(256) k0_w(const float* __restrict__ W) {
    int i = blockIdx.x * 256 + threadIdx.x;
    if (i >= DS * DDIM) return;
    float v = W[i];
    __nv_bfloat16 h = __float2bfloat16(v);
    g_WB_hi[i] = h;
    g_WB_lo[i] = __float2bfloat16(v - __bfloat162float(h));
}

// ---------------------------------------------------------------------------
// K1 W ring issue: stage W chunk c (64 rows x 128B, hi+lo) into buf[c%3]
// ---------------------------------------------------------------------------
__device__ __forceinline__ void k1w_issue(uint32_t smB, int c, int tid) {
    const uint32_t dst = smB + (uint32_t)(c % 3) * 16384u;
    const int kk = c * 64;
    #pragma unroll
    for (int i = 0; i < 2; i++) {
        int v = tid + i * 256;                  // 0..511
        int row = v >> 3, kq8 = v & 7;
        uint32_t off = SWZ(row, kq8 * 16);
        CP16(dst + off,        g_WB_hi + (size_t)row * DDIM + kk + kq8 * 8);
        CP16(dst + 8192 + off, g_WB_lo + (size_t)row * DDIM + kk + kq8 * 8);
    }
    CP_COMMIT();
}

// ---------------------------------------------------------------------------
// K1: h = x @ W^T + b. M=64/CTA (grid 256). x A-frags loaded register-direct
// from global + split in regs; W via cp.async depth-3 ring, 1 sync/chunk.
// Ring schedule per iter c: wait(buf c) -> sync (frees buf (c-1)%3) ->
// issue c+2 into (c+2)%3 == (c-1)%3 -> compute.
// ---------------------------------------------------------------------------
__global__ void __launch_bounds__(256) k1_mma(const float* __restrict__ x,
                                             const float* __restrict__ bias) {
    extern __shared__ __align__(16) char sm1[];
    const int tid = threadIdx.x;
    const int lane = tid & 31;
    const int w = tid >> 5;
    const int wtok = w >> 1;       // 0..3 -> 16 rows each
    const int nhalf = w & 1;       // 0..1 -> 32 cols each
    const int rowBase = blockIdx.x * 64;
    const uint32_t smB = smem_u32(sm1);

    k1w_issue(smB, 0, tid);
    k1w_issue(smB, 1, tid);

    float acc[4][4] = {};
    const float* xr0 = x + (size_t)(rowBase + wtok * 16 + (lane >> 2)) * DDIM
                         + 2 * (lane & 3);
    const float* xr1 = xr0 + 8 * DDIM;

    for (int c = 0; c < K1_NCHUNK; c++) {
        // issue x loads for chunk c before the waits (latency overlap)
        float2 xv[16];
        const int kb = c * 64;
        #pragma unroll
        for (int ks = 0; ks < 4; ks++) {
            xv[ks * 4 + 0] = *(const float2*)(xr0 + kb + ks * 16);
            xv[ks * 4 + 1] = *(const float2*)(xr1 + kb + ks * 16);
            xv[ks * 4 + 2] = *(const float2*)(xr0 + kb + ks * 16 + 8);
            xv[ks * 4 + 3] = *(const float2*)(xr1 + kb + ks * 16 + 8);
        }
        if (c + 1 < K1_NCHUNK) { CP_WAIT1(); } else { CP_WAIT0(); }
        __syncthreads();
        if (c + 2 < K1_NCHUNK) k1w_issue(smB, c + 2, tid);

        // in-register bf16 hi/lo split of the A fragments
        uint32_t ah[4][4], al[4][4];
        #pragma unroll
        for (int ks = 0; ks < 4; ks++) {
            #pragma unroll
            for (int j = 0; j < 4; j++) {
                float2 v = xv[ks * 4 + j];
                __nv_bfloat162 h = __floats2bfloat162_rn(v.x, v.y);
                __nv_bfloat162 l = __floats2bfloat162_rn(v.x - __bfloat162float(h.x),
                                                         v.y - __bfloat162float(h.y));
                ah[ks][j] = bits2(h);
                al[ks][j] = bits2(l);
            }
        }

        const uint32_t whB = smB + (uint32_t)(c % 3) * 16384u;
        const uint32_t wlB = whB + 8192;
        #pragma unroll
        for (int ks = 0; ks < 4; ks++) {
            #pragma unroll
            for (int p = 0; p < 2; p++) {
                int R = nhalf * 32 + (2 * p + (lane >= 16 ? 1 : 0)) * 8 + (lane & 7);
                int byte = ks * 32 + ((lane >> 3) & 1) * 16;
                uint32_t bh0, bh1, bh2, bh3, bl0, bl1, bl2, bl3;
                ldsm4(bh0, bh1, bh2, bh3, whB + SWZ(R, byte));
                ldsm4(bl0, bl1, bl2, bl3, wlB + SWZ(R, byte));
                // interleaved issue; per-acc order stays hh, hl, lh
                mma16816(acc[2 * p],     ah[ks], bh0, bh1);
                mma16816(acc[2 * p + 1], ah[ks], bh2, bh3);
                mma16816(acc[2 * p],     ah[ks], bl0, bl1);
                mma16816(acc[2 * p + 1], ah[ks], bl2, bl3);
                mma16816(acc[2 * p],     al[ks], bh0, bh1);
                mma16816(acc[2 * p + 1], al[ks], bh2, bh3);
            }
        }
    }

    // epilogue: + bias, split to bf16 hi/lo, store [m][64]
    #pragma unroll
    for (int n8 = 0; n8 < 4; n8++) {
        int n = nhalf * 32 + n8 * 8 + 2 * (lane & 3);
        int r0 = rowBase + wtok * 16 + (lane >> 2);
        int r1 = r0 + 8;
        float b0 = bias[n], b1 = bias[n + 1];
        float v00 = acc[n8][0] + b0, v01 = acc[n8][1] + b1;
        float v10 = acc[n8][2] + b0, v11 = acc[n8][3] + b1;
        __nv_bfloat162 h0 = __floats2bfloat162_rn(v00, v01);
        __nv_bfloat162 h1 = __floats2bfloat162_rn(v10, v11);
        __nv_bfloat162 l0 = __floats2bfloat162_rn(v00 - __bfloat162float(h0.x),
                                                  v01 - __bfloat162float(h0.y));
        __nv_bfloat162 l1 = __floats2bfloat162_rn(v10 - __bfloat162float(h1.x),
                                                  v11 - __bfloat162float(h1.y));
        *(__nv_bfloat162*)(g_hB_hi + (size_t)r0 * DS + n) = h0;
        *(__nv_bfloat162*)(g_hB_hi + (size_t)r1 * DS + n) = h1;
        *(__nv_bfloat162*)(g_hB_lo + (size_t)r0 * DS + n) = l0;
        *(__nv_bfloat162*)(g_hB_lo + (size_t)r1 * DS + n) = l1;
    }
}

// ---------------------------------------------------------------------------
// K2 cp.async chunk issue (block-cooperative, proven 124.9 build verbatim)
// ---------------------------------------------------------------------------
__device__ __forceinline__ void k2_issue(uint32_t base, int c, int tid) {
    const int nb = c * NCH2;
    const uint32_t dst = base + ((c & 1) ? OFF_BB : OFF_BA);
    #pragma unroll
    for (int i = 0; i < 2; i++) {
        int v = tid + i * 256;
        int row = v >> 3, kq8 = v & 7;
        uint32_t off = SWZ(row, kq8 * 16);
        CP16(dst + off,        g_embB_hi + (size_t)(nb + row) * DS + kq8 * 8);
        CP16(dst + 8192 + off, g_embB_lo + (size_t)(nb + row) * DS + kq8 * 8);
    }
    CP_COMMIT();
}

// ---------------------------------------------------------------------------
// K2: 32 tokens/CTA, A frags in regs, cp.async depth-2 (verbatim).
// ---------------------------------------------------------------------------
__global__ void __launch_bounds__(256) k2_route(const float* __restrict__ imp) {
    extern __shared__ __align__(16) char sm[];
    const uint32_t base = smem_u32(sm);
    float* Ebuf = (float*)(sm + OFF_E2);
    float* zsm  = (float*)(sm + OFF_Z2);
    float* coef = (float*)(sm + OFF_C2);

    const int tid = threadIdx.x;
    const int lane = tid & 31;
    const int w = tid >> 5;
    const int wtok = w >> 2;
    const int q    = w & 3;
    const int bid = blockIdx.x;
    const int tokBase = bid * K2_TOK;

    k2_issue(base, 0, tid);
    k2_issue(base, 1, tid);

    uint32_t ah[4][4], al[4][4];
    {
        const int ra = tokBase + wtok * 16 + (lane >> 2);
        #pragma unroll
        for (int ks = 0; ks < 4; ks++) {
            int kb = ks * 16 + 2 * (lane & 3);
            ah[ks][0] = *(const uint32_t*)(g_hB_hi + (size_t)ra * DS + kb);
            ah[ks][1] = *(const uint32_t*)(g_hB_hi + (size_t)(ra + 8) * DS + kb);
            ah[ks][2] = *(const uint32_t*)(g_hB_hi + (size_t)ra * DS + kb + 8);
            ah[ks][3] = *(const uint32_t*)(g_hB_hi + (size_t)(ra + 8) * DS + kb + 8);
            al[ks][0] = *(const uint32_t*)(g_hB_lo + (size_t)ra * DS + kb);
            al[ks][1] = *(const uint32_t*)(g_hB_lo + (size_t)(ra + 8) * DS + kb);
            al[ks][2] = *(const uint32_t*)(g_hB_lo + (size_t)ra * DS + kb + 8);
            al[ks][3] = *(const uint32_t*)(g_hB_lo + (size_t)(ra + 8) * DS + kb + 8);
        }
    }

    const int gnch[4]  = {8, 8, 4, 4};
    const int gbase[4] = {0, 512, 1024, 1280};
    int chunk = 0;

    for (int grp = 0; grp < 4; grp++) {
        float zr0 = 0.f, zr1 = 0.f;
        for (int ci = 0; ci < gnch[grp]; ci++, chunk++) {
            if (chunk < NCHUNKS2 - 1) { CP_WAIT1(); } else { CP_WAIT0(); }
            __syncthreads();

            const uint32_t bhB = base + ((chunk & 1) ? OFF_BB : OFF_BA);
            const uint32_t blB = bhB + 8192;

            float acc[2][4] = {};
            #pragma unroll
            for (int ks = 0; ks < 4; ks++) {
                int R = q * 16 + (lane >= 16 ? 8 : 0) + (lane & 7);
                int byte = ks * 32 + ((lane >> 3) & 1) * 16;
                uint32_t bh0, bh1, bh2, bh3, bl0, bl1, bl2, bl3;
                ldsm4(bh0, bh1, bh2, bh3, bhB + SWZ(R, byte));
                ldsm4(bl0, bl1, bl2, bl3, blB + SWZ(R, byte));
                mma16816(acc[0], ah[ks], bh0, bh1);
                mma16816(acc[1], ah[ks], bh2, bh3);
                mma16816(acc[0], ah[ks], bl0, bl1);
                mma16816(acc[1], ah[ks], bl2, bl3);
                mma16816(acc[0], al[ks], bh0, bh1);
                mma16816(acc[1], al[ks], bh2, bh3);
            }

            const int r0 = wtok * 16 + (lane >> 2);
            #pragma unroll
            for (int n8 = 0; n8 < 2; n8++) {
                int colg = ci * NCH2 + q * 16 + n8 * 8 + 2 * (lane & 3);
                float e00 = __expf(acc[n8][0]);
                float e01 = __expf(acc[n8][1]);
                float e10 = __expf(acc[n8][2]);
                float e11 = __expf(acc[n8][3]);
                *(float2*)(Ebuf + (size_t)r0 * EPH + colg)       = make_float2(e00, e01);
                *(float2*)(Ebuf + (size_t)(r0 + 8) * EPH + colg) = make_float2(e10, e11);
                zr0 += e00 + e01;
                zr1 += e10 + e11;
            }

            __syncthreads();
            if (chunk + 2 < NCHUNKS2) k2_issue(base, chunk + 2, tid);
        }
        zr0 += __shfl_xor_sync(0xFFFFFFFFu, zr0, 1);
        zr0 += __shfl_xor_sync(0xFFFFFFFFu, zr0, 2);
        zr1 += __shfl_xor_sync(0xFFFFFFFFu, zr1, 1);
        zr1 += __shfl_xor_sync(0xFFFFFFFFu, zr1, 2);
        {
            const int r0 = wtok * 16 + (lane >> 2);
            if ((lane & 3) == 0) {
                zsm[r0 * 4 + q]       = zr0;
                zsm[(r0 + 8) * 4 + q] = zr1;
            }
        }
        __syncthreads();
        if (tid < K2_TOK)
            coef[tid] = imp[tokBase + tid] /
                        (zsm[4 * tid] + zsm[4 * tid + 1] + zsm[4 * tid + 2] + zsm[4 * tid + 3]);
        __syncthreads();

        {
            const int halfw = (gnch[grp] * NCH2) >> 1;
            for (int np = tid; np < halfw; np += 256) {
                const float2* ecol = (const float2*)Ebuf + np;
                float s0 = 0.f, s1 = 0.f;
                #pragma unroll 8
                for (int t = 0; t < K2_TOK; t++) {
                    float2 f = ecol[t * (EPH / 2)];
                    float c = coef[t];
                    s0 += c * f.x;
                    s1 += c * f.y;
                }
                size_t o = (size_t)bid * NUSE + gbase[grp] + 2 * np;
                g_part[o]     = s0;
                g_part[o + 1] = s1;
            }
        }
    }
}

// ---------------------------------------------------------------------------
// K3: per (batch,group) reduce partials + top-k + renormalize + scatter.
// ---------------------------------------------------------------------------
__global__ void __launch_bounds__(256) k3_topk(float* __restrict__ out) {
    const int gs_[4]  = {0, 512, 1024, 1280};
    const int gl_[4]  = {512, 512, 256, 256};
    const int kk_[4]  = {8, 8, 4, 6};
    const int oo_[4]  = {0, 512, 1024, 1536};

    int task = blockIdx.x;
    int b = task >> 2, g = task & 3;
    int len = gl_[g], K = kk_[g];

    __shared__ float sv[512];
    __shared__ float wv[512];
    __shared__ unsigned char sel[512];
    __shared__ float red[8];
    __shared__ int   redi[8];
    __shared__ float s_ksum;

    const float* pb = g_part + (size_t)b * BLK_PER_B * NUSE + gs_[g];
    for (int i = threadIdx.x; i < len; i += 256) {
        float v = 0.f;
        #pragma unroll 8
        for (int j = 0; j < BLK_PER_B; j++) v += pb[(size_t)j * NUSE + i];
        sv[i] = v; wv[i] = v; sel[i] = 0;
    }
    if (threadIdx.x == 0) s_ksum = 0.f;
    __syncthreads();

    for (int it = 0; it < K; it++) {
        float best = -1e30f; int bi = 0x7FFFFFFF;
        for (int i = threadIdx.x; i < len; i += 256) {
            float v = wv[i];
            if (v > best || (v == best && i < bi)) { best = v; bi = i; }
        }
        #pragma unroll
        for (int o = 16; o; o >>= 1) {
            float ov = __shfl_xor_sync(0xFFFFFFFFu, best, o);
            int   oi = __shfl_xor_sync(0xFFFFFFFFu, bi,   o);
            if (ov > best || (ov == best && oi < bi)) { best = ov; bi = oi; }
        }
        if ((threadIdx.x & 31) == 0) { red[threadIdx.x >> 5] = best; redi[threadIdx.x >> 5] = bi; }
        __syncthreads();
        if (threadIdx.x == 0) {
            float bb = red[0]; int bbi = redi[0];
            for (int ww = 1; ww < 8; ww++)
                if (red[ww] > bb || (red[ww] == bb && redi[ww] < bbi)) { bb = red[ww]; bbi = redi[ww]; }
            sel[bbi] = 1; wv[bbi] = -1e30f; s_ksum += sv[bbi];
        }
        __syncthreads();
    }

    float inv = 1.0f / (s_ksum + 1e-8f);
    float* ob = out + b * OUT_PER_B;
    for (int i = threadIdx.x; i < len; i += 256) {
        float o = sel[i] ? sv[i] * inv : 0.0f;
        ob[oo_[g] + i] = o;
        if (g == 2) ob[1280 + i] = o;
    }
}

// ---------------------------------------------------------------------------
extern "C" void kernel_launch(void* const* d_in, const int* in_sizes, int n_in,
                              void* d_out, int out_size) {
    const float* x    = (const float*)d_in[0];
    const float* imp  = (const float*)d_in[1];
    const float* W    = (const float*)d_in[2];
    const float* bias = (const float*)d_in[3];
    const float* emb  = (const float*)d_in[4];
    float* out = (float*)d_out;
    (void)in_sizes; (void)n_in; (void)out_size;

    (void)cudaFuncSetAttribute(k1_mma, cudaFuncAttributeMaxDynamicSharedMemorySize,
                               K1_SMEM);
    (void)cudaFuncSetAttribute(k2_route, cudaFuncAttributeMaxDynamicSharedMemorySize,
                               K2_SMEM);

    k0_norm<<<NUSE / 8, 256>>>(emb);
    k0_w<<<(DS * DDIM) / 256, 256>>>(W);
    k1_mma<<<NTOK_TOTAL / 64, 256, K1_SMEM>>>(x, bias);
    k2_route<<<K2_BLOCKS, 256, K2_SMEM>>>(imp);
    k3_topk<<<BATCHES * 4, 256>>>(out);
}